// round 1
// baseline (speedup 1.0000x reference)
#include <cuda_runtime.h>
#include <math.h>

#define BB 64
#define NN 512
#define EE 128
#define FEATN 33
#define ROWS (BB*NN)
#define LARGEF 1000000.0f

__device__ float g_validf[ROWS];
__device__ float g_feat[(size_t)ROWS * FEATN];
__device__ int   g_maskmode;

// ---------------------------------------------------------------------------
// Mask dtype detection: bool array may arrive as u8 / i32 / f32. Scan only the
// first 8192 32-bit words (guaranteed present in all three layouts).
// u8  layout -> words composed of bytes {0,1}: some word >1 (e.g. 256) and never 0x3F800000
// f32 layout -> words in {0, 0x3F800000}
// i32 layout -> words in {0, 1}
// ---------------------------------------------------------------------------
__global__ void detect_mask_kernel(const unsigned* __restrict__ mw) {
    __shared__ int sU, sF;
    if (threadIdx.x == 0) { sU = 0; sF = 0; }
    __syncthreads();
    int u = 0, f = 0;
    for (int idx = threadIdx.x; idx < 8192; idx += blockDim.x) {
        unsigned w = mw[idx];
        if (w == 0x3F800000u) f = 1;
        else if (w > 1u) u = 1;
    }
    if (u) atomicOr(&sU, 1);
    if (f) atomicOr(&sF, 1);
    __syncthreads();
    if (threadIdx.x == 0) g_maskmode = sU ? 1 : (sF ? 2 : 0);
}

__global__ void expand_mask_kernel(const void* __restrict__ mask) {
    int idx = blockIdx.x * blockDim.x + threadIdx.x;
    if (idx >= ROWS) return;
    int mode = g_maskmode;
    bool m;
    if (mode == 1)      m = ((const unsigned char*)mask)[idx] != 0;
    else if (mode == 2) m = ((const float*)mask)[idx] != 0.0f;
    else                m = ((const int*)mask)[idx] != 0;
    g_validf[idx] = m ? 0.0f : 1.0f;
}

// ---------------------------------------------------------------------------
// Feature kernel: one warp per (b, i) row; lanes stride over j.
// ---------------------------------------------------------------------------
__device__ __forceinline__ float wsum(float v) {
#pragma unroll
    for (int o = 16; o > 0; o >>= 1) v += __shfl_xor_sync(0xFFFFFFFFu, v, o);
    return v;
}
__device__ __forceinline__ float wmin(float v) {
#pragma unroll
    for (int o = 16; o > 0; o >>= 1) v = fminf(v, __shfl_xor_sync(0xFFFFFFFFu, v, o));
    return v;
}

__global__ __launch_bounds__(256) void feat_kernel(const float* __restrict__ pos) {
    __shared__ float4 sp[NN];
    const int b   = blockIdx.y;
    const int tid = threadIdx.x;

    for (int idx = tid; idx < NN; idx += 256) {
        float px = pos[(b * NN + idx) * 2 + 0];
        float py = pos[(b * NN + idx) * 2 + 1];
        sp[idx] = make_float4(px, py, g_validf[b * NN + idx], 0.0f);
    }
    __syncthreads();

    const int warp = tid >> 5, lane = tid & 31;
    const int i = blockIdx.x * 8 + warp;
    const float4 pi = sp[i];
    const float xi = pi.x, yi = pi.y;

    unsigned long long cntDT = 0ull;   // 12 counters: dir(0/20/40) x thresh(5-bit fields)
    unsigned scntLo = 0u, scntHi = 0u; // 8 sector counters, 8-bit fields
    float mdUp = LARGEF, mdDn = LARGEF, mdLat = LARGEF;
    float smin[8];
#pragma unroll
    for (int k = 0; k < 8; k++) smin[k] = LARGEF;
    float sumd = 0.0f, cntv = 0.0f;

#pragma unroll 4
    for (int j0 = 0; j0 < 16; j0++) {
        const int j = lane + (j0 << 5);
        const float4 p = sp[j];
        const float dx = p.x - xi;
        const float dy = p.y - yi;
        // match reference: dx*dx + dy*dy + 1e-8, no FMA contraction, IEEE sqrt
        const float d2   = __fadd_rn(__fadd_rn(__fmul_rn(dx, dx), __fmul_rn(dy, dy)), 1e-8f);
        const float dist = sqrtf(d2);
        const bool  valid = (p.z != 0.0f) && (j != i);
        const float dmod  = valid ? dist : LARGEF;

        // direction classes
        const float hay = 0.5f * fabsf(dy);
        const bool up = dx >  hay;
        const bool dn = dx < -hay;

        // cumulative threshold pattern (fields at bits 0/5/10/15 for 3/5/8/12)
        unsigned pat = (dmod < 3.0f) ? 0x8421u
                     : (dmod < 5.0f) ? 0x8420u
                     : (dmod < 8.0f) ? 0x8400u
                     : (dmod < 12.0f) ? 0x8000u : 0u;
        const int dsh = up ? 0 : (dn ? 20 : 40);
        cntDT += (unsigned long long)pat << dsh;

        mdUp  = fminf(mdUp,  up ? dmod : LARGEF);
        mdDn  = fminf(mdDn,  dn ? dmod : LARGEF);
        mdLat = fminf(mdLat, (!up && !dn) ? dmod : LARGEF);

        // sector (octant) via sign tests — matches atan2 vs linspace(-pi,pi,9) edges
        const float su = dx + dy, sv = dy - dx;
        const int s = (dy < 0.0f)
            ? ((dx < 0.0f) ? ((sv > 0.0f) ? 0 : 1) : ((su < 0.0f) ? 2 : 3))
            : ((dx > 0.0f) ? ((sv < 0.0f) ? 4 : 5) : ((su > 0.0f) ? 6 : 7));

        const unsigned sinc = valid ? (1u << ((s & 3) << 3)) : 0u;
        if (s < 4) scntLo += sinc; else scntHi += sinc;
#pragma unroll
        for (int k = 0; k < 8; k++)
            if (s == k) smin[k] = fminf(smin[k], dmod);

        if (valid) { sumd += dist; cntv += 1.0f; }
    }

    // unpack + warp reduce
    float cnt[12];
#pragma unroll
    for (int d = 0; d < 3; d++)
#pragma unroll
        for (int t = 0; t < 4; t++)
            cnt[d * 4 + t] = (float)((unsigned)(cntDT >> (d * 20 + t * 5)) & 31u);
    float sc[8];
#pragma unroll
    for (int k = 0; k < 8; k++)
        sc[k] = (float)(((k < 4 ? (scntLo >> (k * 8)) : (scntHi >> ((k - 4) * 8)))) & 255u);

#pragma unroll
    for (int q = 0; q < 12; q++) cnt[q] = wsum(cnt[q]);
#pragma unroll
    for (int k = 0; k < 8; k++) { sc[k] = wsum(sc[k]); smin[k] = wmin(smin[k]); }
    mdUp = wmin(mdUp); mdDn = wmin(mdDn); mdLat = wmin(mdLat);
    sumd = wsum(sumd); cntv = wsum(cntv);

    if (lane == 0) {
        float* o = g_feat + (size_t)(b * NN + i) * FEATN;
#pragma unroll
        for (int t = 0; t < 4; t++) {
            o[t * 3 + 0] = cnt[0 * 4 + t];
            o[t * 3 + 1] = cnt[1 * 4 + t];
            o[t * 3 + 2] = cnt[2 * 4 + t];
        }
        o[12] = fminf(mdUp / 10.0f, 1.0f);
        o[13] = fminf(mdDn / 10.0f, 1.0f);
        o[14] = fminf(mdLat / 10.0f, 1.0f);
#pragma unroll
        for (int k = 0; k < 8; k++) {
            o[15 + 2 * k] = sc[k];
            o[16 + 2 * k] = fminf(smin[k] / 10.0f, 1.0f);
        }
        o[31] = cnt[3] + cnt[7] + cnt[11];   // n_neighbors (thresh=12, all dirs)
        float vc = fmaxf(cntv, 1.0f);
        o[32] = fminf(sumd / vc / 10.0f, 1.0f);
    }
}

// ---------------------------------------------------------------------------
// Encoder: per block 32 rows.  h = x@W1+b1 -> LN -> GELU(erf) -> @W2+b2
// Shared: W2 [128][129], h [32][132], x [32][33], LN partials [32][8]
// ---------------------------------------------------------------------------
#define W2S 0
#define HS  16512
#define XS  20736
#define RED 21792
#define SHWORDS 22048

__global__ __launch_bounds__(256) void encoder_kernel(
    const float* __restrict__ W1, const float* __restrict__ b1,
    const float* __restrict__ gamma, const float* __restrict__ beta,
    const float* __restrict__ W2, const float* __restrict__ b2,
    float* __restrict__ out)
{
    extern __shared__ float shm[];
    const int tid  = threadIdx.x;
    const int c    = tid & 127;
    const int half = tid >> 7;
    const int lane = tid & 31;
    const int wh   = (tid >> 5) & 3;   // warp index within half
    const int rowBase = blockIdx.x * 32;

    for (int idx = tid; idx < EE * EE; idx += 256) {
        int k = idx >> 7, cc = idx & 127;
        shm[W2S + k * 129 + cc] = W2[idx];
    }
    for (int idx = tid; idx < 32 * FEATN; idx += 256)
        shm[XS + idx] = g_feat[(size_t)rowBase * FEATN + idx];
    __syncthreads();

    // GEMM1: 16 rows per thread, column c
    float acc[16];
    {
        const float bc = __ldg(&b1[c]);
#pragma unroll
        for (int rr = 0; rr < 16; rr++) acc[rr] = bc;
        for (int f = 0; f < FEATN; f++) {
            const float w = __ldg(&W1[f * EE + c]);
#pragma unroll
            for (int rr = 0; rr < 16; rr++)
                acc[rr] += shm[XS + (half * 16 + rr) * FEATN + f] * w;
        }
    }

    // LN partials per row (sum, sumsq) across this warp's 32 columns
#pragma unroll
    for (int rr = 0; rr < 16; rr++) {
        float s  = wsum(acc[rr]);
        float sq = wsum(acc[rr] * acc[rr]);
        if (lane == 0) {
            int r = half * 16 + rr;
            shm[RED + r * 8 + wh * 2 + 0] = s;
            shm[RED + r * 8 + wh * 2 + 1] = sq;
        }
    }
    __syncthreads();

    const float g  = __ldg(&gamma[c]);
    const float be = __ldg(&beta[c]);
#pragma unroll
    for (int rr = 0; rr < 16; rr++) {
        int r = half * 16 + rr;
        float s = 0.0f, sq = 0.0f;
#pragma unroll
        for (int w = 0; w < 4; w++) {
            s  += shm[RED + r * 8 + w * 2 + 0];
            sq += shm[RED + r * 8 + w * 2 + 1];
        }
        const float mu  = s * (1.0f / 128.0f);
        const float var = sq * (1.0f / 128.0f) - mu * mu;
        float hn = (acc[rr] - mu) / sqrtf(var + 1e-5f) * g + be;
        hn = 0.5f * hn * (1.0f + erff(hn * 0.70710678118654752440f));
        shm[HS + r * 132 + c] = hn;
    }
    __syncthreads();

    // GEMM2: 16 rows per thread, column c, k vectorized by 4
    float oacc[16];
    {
        const float bo = __ldg(&b2[c]);
#pragma unroll
        for (int rr = 0; rr < 16; rr++) oacc[rr] = bo;
        for (int k4 = 0; k4 < EE; k4 += 4) {
            const float w0 = shm[W2S + (k4 + 0) * 129 + c];
            const float w1 = shm[W2S + (k4 + 1) * 129 + c];
            const float w2 = shm[W2S + (k4 + 2) * 129 + c];
            const float w3 = shm[W2S + (k4 + 3) * 129 + c];
#pragma unroll
            for (int rr = 0; rr < 16; rr++) {
                const float4 hv = *(const float4*)&shm[HS + (half * 16 + rr) * 132 + k4];
                oacc[rr] += hv.x * w0 + hv.y * w1 + hv.z * w2 + hv.w * w3;
            }
        }
    }
#pragma unroll
    for (int rr = 0; rr < 16; rr++)
        out[(size_t)(rowBase + half * 16 + rr) * EE + c] = oacc[rr];
}

// ---------------------------------------------------------------------------
extern "C" void kernel_launch(void* const* d_in, const int* in_sizes, int n_in,
                              void* d_out, int out_size) {
    const float* positions = (const float*)d_in[0];
    const void*  mask      = d_in[1];
    const float* W1        = (const float*)d_in[2];
    const float* b1        = (const float*)d_in[3];
    const float* gamma     = (const float*)d_in[4];
    const float* beta      = (const float*)d_in[5];
    const float* W2        = (const float*)d_in[6];
    const float* b2        = (const float*)d_in[7];
    float* out = (float*)d_out;

    detect_mask_kernel<<<1, 256>>>((const unsigned*)mask);
    expand_mask_kernel<<<ROWS / 256, 256>>>(mask);
    feat_kernel<<<dim3(NN / 8, BB), 256>>>(positions);

    const size_t shbytes = (size_t)SHWORDS * 4;
    cudaFuncSetAttribute(encoder_kernel, cudaFuncAttributeMaxDynamicSharedMemorySize, (int)shbytes);
    encoder_kernel<<<ROWS / 32, 256, shbytes>>>(W1, b1, gamma, beta, W2, b2, out);
}

// round 2
// speedup vs baseline: 1.1641x; 1.1641x over previous
#include <cuda_runtime.h>
#include <math.h>

#define BB 64
#define NN 512
#define EE 128
#define FEATN 33
#define ROWS (BB*NN)
#define LARGEF 1000000.0f

__device__ float g_validf[ROWS];
__device__ float g_feat[(size_t)ROWS * FEATN];
__device__ int   g_maskmode;

// ---------------------------------------------------------------------------
// Mask dtype detection (u8 / i32 / f32). Scan first 8192 words (present in all).
// ---------------------------------------------------------------------------
__global__ void detect_mask_kernel(const unsigned* __restrict__ mw) {
    __shared__ int sU, sF;
    if (threadIdx.x == 0) { sU = 0; sF = 0; }
    __syncthreads();
    int u = 0, f = 0;
    for (int idx = threadIdx.x; idx < 8192; idx += blockDim.x) {
        unsigned w = mw[idx];
        if (w == 0x3F800000u) f = 1;
        else if (w > 1u) u = 1;
    }
    if (u) atomicOr(&sU, 1);
    if (f) atomicOr(&sF, 1);
    __syncthreads();
    if (threadIdx.x == 0) g_maskmode = sU ? 1 : (sF ? 2 : 0);
}

__global__ void expand_mask_kernel(const void* __restrict__ mask) {
    int idx = blockIdx.x * blockDim.x + threadIdx.x;
    if (idx >= ROWS) return;
    int mode = g_maskmode;
    bool m;
    if (mode == 1)      m = ((const unsigned char*)mask)[idx] != 0;
    else if (mode == 2) m = ((const float*)mask)[idx] != 0.0f;
    else                m = ((const int*)mask)[idx] != 0;
    g_validf[idx] = m ? 0.0f : 1.0f;
}

// ---------------------------------------------------------------------------
// Feature kernel: one warp per (b, i) row; lanes stride over j.
// ---------------------------------------------------------------------------
__device__ __forceinline__ float wsum(float v) {
#pragma unroll
    for (int o = 16; o > 0; o >>= 1) v += __shfl_xor_sync(0xFFFFFFFFu, v, o);
    return v;
}
__device__ __forceinline__ float wmin(float v) {
#pragma unroll
    for (int o = 16; o > 0; o >>= 1) v = fminf(v, __shfl_xor_sync(0xFFFFFFFFu, v, o));
    return v;
}

__global__ __launch_bounds__(256) void feat_kernel(const float* __restrict__ pos) {
    __shared__ float4 sp[NN];
    const int b   = blockIdx.y;
    const int tid = threadIdx.x;

    for (int idx = tid; idx < NN; idx += 256) {
        float px = pos[(b * NN + idx) * 2 + 0];
        float py = pos[(b * NN + idx) * 2 + 1];
        sp[idx] = make_float4(px, py, g_validf[b * NN + idx], 0.0f);
    }
    __syncthreads();

    const int warp = tid >> 5, lane = tid & 31;
    const int i = blockIdx.x * 8 + warp;
    const float4 pi = sp[i];
    const float xi = pi.x, yi = pi.y;

    unsigned long long cntDT = 0ull;   // 12 counters: dir(0/20/40) x thresh(5-bit fields)
    unsigned scntLo = 0u, scntHi = 0u; // 8 sector counters, 8-bit fields
    float mdUp = LARGEF, mdDn = LARGEF, mdLat = LARGEF;
    float smin[8];
#pragma unroll
    for (int k = 0; k < 8; k++) smin[k] = LARGEF;
    float sumd = 0.0f, cntv = 0.0f;

#pragma unroll 4
    for (int j0 = 0; j0 < 16; j0++) {
        const int j = lane + (j0 << 5);
        const float4 p = sp[j];
        const float dx = p.x - xi;
        const float dy = p.y - yi;
        const float d2   = __fadd_rn(__fadd_rn(__fmul_rn(dx, dx), __fmul_rn(dy, dy)), 1e-8f);
        const float dist = sqrtf(d2);
        const bool  valid = (p.z != 0.0f) && (j != i);
        const float dmod  = valid ? dist : LARGEF;

        const float hay = 0.5f * fabsf(dy);
        const bool up = dx >  hay;
        const bool dn = dx < -hay;

        unsigned pat = (dmod < 3.0f) ? 0x8421u
                     : (dmod < 5.0f) ? 0x8420u
                     : (dmod < 8.0f) ? 0x8400u
                     : (dmod < 12.0f) ? 0x8000u : 0u;
        const int dsh = up ? 0 : (dn ? 20 : 40);
        cntDT += (unsigned long long)pat << dsh;

        mdUp  = fminf(mdUp,  up ? dmod : LARGEF);
        mdDn  = fminf(mdDn,  dn ? dmod : LARGEF);
        mdLat = fminf(mdLat, (!up && !dn) ? dmod : LARGEF);

        const float su = dx + dy, sv = dy - dx;
        const int s = (dy < 0.0f)
            ? ((dx < 0.0f) ? ((sv > 0.0f) ? 0 : 1) : ((su < 0.0f) ? 2 : 3))
            : ((dx > 0.0f) ? ((sv < 0.0f) ? 4 : 5) : ((su > 0.0f) ? 6 : 7));

        const unsigned sinc = valid ? (1u << ((s & 3) << 3)) : 0u;
        if (s < 4) scntLo += sinc; else scntHi += sinc;
#pragma unroll
        for (int k = 0; k < 8; k++)
            if (s == k) smin[k] = fminf(smin[k], dmod);

        if (valid) { sumd += dist; cntv += 1.0f; }
    }

    float cnt[12];
#pragma unroll
    for (int d = 0; d < 3; d++)
#pragma unroll
        for (int t = 0; t < 4; t++)
            cnt[d * 4 + t] = (float)((unsigned)(cntDT >> (d * 20 + t * 5)) & 31u);
    float sc[8];
#pragma unroll
    for (int k = 0; k < 8; k++)
        sc[k] = (float)(((k < 4 ? (scntLo >> (k * 8)) : (scntHi >> ((k - 4) * 8)))) & 255u);

#pragma unroll
    for (int q = 0; q < 12; q++) cnt[q] = wsum(cnt[q]);
#pragma unroll
    for (int k = 0; k < 8; k++) { sc[k] = wsum(sc[k]); smin[k] = wmin(smin[k]); }
    mdUp = wmin(mdUp); mdDn = wmin(mdDn); mdLat = wmin(mdLat);
    sumd = wsum(sumd); cntv = wsum(cntv);

    if (lane == 0) {
        float* o = g_feat + (size_t)(b * NN + i) * FEATN;
#pragma unroll
        for (int t = 0; t < 4; t++) {
            o[t * 3 + 0] = cnt[0 * 4 + t];
            o[t * 3 + 1] = cnt[1 * 4 + t];
            o[t * 3 + 2] = cnt[2 * 4 + t];
        }
        o[12] = fminf(mdUp / 10.0f, 1.0f);
        o[13] = fminf(mdDn / 10.0f, 1.0f);
        o[14] = fminf(mdLat / 10.0f, 1.0f);
#pragma unroll
        for (int k = 0; k < 8; k++) {
            o[15 + 2 * k] = sc[k];
            o[16 + 2 * k] = fminf(smin[k] / 10.0f, 1.0f);
        }
        o[31] = cnt[3] + cnt[7] + cnt[11];
        float vc = fmaxf(cntv, 1.0f);
        o[32] = fminf(sumd / vc / 10.0f, 1.0f);
    }
}

// ---------------------------------------------------------------------------
// Encoder v2: 32 rows/block, 256 threads (c = tid&127, half = tid>>7).
// W1/W2 read directly from global (__ldg, L1-resident: 81KB total).
// Shared: x[32][36] (padded for float4), h[32][132], LN partials [32][8].
// smem ~22.6KB -> 6 CTAs/SM (reg-limited), ~75% occupancy.
// ---------------------------------------------------------------------------
#define XPITCH 36
#define HPITCH 132

__global__ __launch_bounds__(256, 6) void encoder_kernel(
    const float* __restrict__ W1, const float* __restrict__ b1,
    const float* __restrict__ gamma, const float* __restrict__ beta,
    const float* __restrict__ W2, const float* __restrict__ b2,
    float* __restrict__ out)
{
    __shared__ float sx[32 * XPITCH];
    __shared__ float sh[32 * HPITCH];
    __shared__ float sred[32 * 8];

    const int tid  = threadIdx.x;
    const int c    = tid & 127;
    const int half = tid >> 7;
    const int lane = tid & 31;
    const int wh   = (tid >> 5) & 3;
    const int rowBase = blockIdx.x * 32;

    // stage x (33 feats/row, padded pitch 36)
    for (int idx = tid; idx < 32 * FEATN; idx += 256) {
        int r = idx / FEATN, f = idx - r * FEATN;
        sx[r * XPITCH + f] = g_feat[(size_t)rowBase * FEATN + idx];
    }
    // zero padding columns so float4 tail reads are harmless
    if (tid < 32 * 3) {
        int r = tid / 3, f = FEATN + tid % 3;
        sx[r * XPITCH + f] = 0.0f;
    }
    __syncthreads();

    // GEMM1: 16 rows per thread, column c. k vectorized by 4 (f=0..35, pad=0).
    float acc[16];
    {
        const float bc = __ldg(&b1[c]);
#pragma unroll
        for (int rr = 0; rr < 16; rr++) acc[rr] = bc;
#pragma unroll 3
        for (int f4 = 0; f4 < 32; f4 += 4) {
            const float w0 = __ldg(&W1[(f4 + 0) * EE + c]);
            const float w1 = __ldg(&W1[(f4 + 1) * EE + c]);
            const float w2 = __ldg(&W1[(f4 + 2) * EE + c]);
            const float w3 = __ldg(&W1[(f4 + 3) * EE + c]);
#pragma unroll
            for (int rr = 0; rr < 16; rr++) {
                const float4 xv = *(const float4*)&sx[(half * 16 + rr) * XPITCH + f4];
                acc[rr] += xv.x * w0 + xv.y * w1 + xv.z * w2 + xv.w * w3;
            }
        }
        const float wl = __ldg(&W1[32 * EE + c]);  // f = 32 tail
#pragma unroll
        for (int rr = 0; rr < 16; rr++)
            acc[rr] += sx[(half * 16 + rr) * XPITCH + 32] * wl;
    }

    // LN partials per row (sum, sumsq) across this warp's 32 columns
#pragma unroll
    for (int rr = 0; rr < 16; rr++) {
        float s  = wsum(acc[rr]);
        float sq = wsum(acc[rr] * acc[rr]);
        if (lane == 0) {
            int r = half * 16 + rr;
            sred[r * 8 + wh * 2 + 0] = s;
            sred[r * 8 + wh * 2 + 1] = sq;
        }
    }
    __syncthreads();

    const float g  = __ldg(&gamma[c]);
    const float be = __ldg(&beta[c]);
#pragma unroll
    for (int rr = 0; rr < 16; rr++) {
        int r = half * 16 + rr;
        float s = 0.0f, sq = 0.0f;
#pragma unroll
        for (int w = 0; w < 4; w++) {
            s  += sred[r * 8 + w * 2 + 0];
            sq += sred[r * 8 + w * 2 + 1];
        }
        const float mu  = s * (1.0f / 128.0f);
        const float var = sq * (1.0f / 128.0f) - mu * mu;
        float hn = (acc[rr] - mu) / sqrtf(var + 1e-5f) * g + be;
        hn = 0.5f * hn * (1.0f + erff(hn * 0.70710678118654752440f));
        sh[r * HPITCH + c] = hn;
    }
    __syncthreads();

    // GEMM2: 16 rows per thread, column c, W2 from L1 via __ldg, h from shared
    float oacc[16];
    {
        const float bo = __ldg(&b2[c]);
#pragma unroll
        for (int rr = 0; rr < 16; rr++) oacc[rr] = bo;
#pragma unroll 2
        for (int k4 = 0; k4 < EE; k4 += 4) {
            const float w0 = __ldg(&W2[(k4 + 0) * EE + c]);
            const float w1 = __ldg(&W2[(k4 + 1) * EE + c]);
            const float w2 = __ldg(&W2[(k4 + 2) * EE + c]);
            const float w3 = __ldg(&W2[(k4 + 3) * EE + c]);
#pragma unroll
            for (int rr = 0; rr < 16; rr++) {
                const float4 hv = *(const float4*)&sh[(half * 16 + rr) * HPITCH + k4];
                oacc[rr] += hv.x * w0 + hv.y * w1 + hv.z * w2 + hv.w * w3;
            }
        }
    }
#pragma unroll
    for (int rr = 0; rr < 16; rr++)
        out[(size_t)(rowBase + half * 16 + rr) * EE + c] = oacc[rr];
}

// ---------------------------------------------------------------------------
extern "C" void kernel_launch(void* const* d_in, const int* in_sizes, int n_in,
                              void* d_out, int out_size) {
    const float* positions = (const float*)d_in[0];
    const void*  mask      = d_in[1];
    const float* W1        = (const float*)d_in[2];
    const float* b1        = (const float*)d_in[3];
    const float* gamma     = (const float*)d_in[4];
    const float* beta      = (const float*)d_in[5];
    const float* W2        = (const float*)d_in[6];
    const float* b2        = (const float*)d_in[7];
    float* out = (float*)d_out;

    detect_mask_kernel<<<1, 256>>>((const unsigned*)mask);
    expand_mask_kernel<<<ROWS / 256, 256>>>(mask);
    feat_kernel<<<dim3(NN / 8, BB), 256>>>(positions);
    encoder_kernel<<<ROWS / 32, 256>>>(W1, b1, gamma, beta, W2, b2, out);
}

// round 3
// speedup vs baseline: 1.2677x; 1.0890x over previous
#include <cuda_runtime.h>
#include <math.h>

#define BB 64
#define NN 512
#define EE 128
#define FEATN 33
#define ROWS (BB*NN)
#define LARGEF 1000000.0f

__device__ float g_feat[(size_t)ROWS * FEATN];
__device__ int   g_maskmode;

// ---------------------------------------------------------------------------
// Mask dtype detection (u8 / i32 / f32). Scan first 8192 words (present in all).
// ---------------------------------------------------------------------------
__global__ void detect_mask_kernel(const unsigned* __restrict__ mw) {
    __shared__ int sU, sF;
    if (threadIdx.x == 0) { sU = 0; sF = 0; }
    __syncthreads();
    int u = 0, f = 0;
    for (int idx = threadIdx.x; idx < 8192; idx += blockDim.x) {
        unsigned w = mw[idx];
        if (w == 0x3F800000u) f = 1;
        else if (w > 1u) u = 1;
    }
    if (u) atomicOr(&sU, 1);
    if (f) atomicOr(&sF, 1);
    __syncthreads();
    if (threadIdx.x == 0) g_maskmode = sU ? 1 : (sF ? 2 : 0);
}

// ---------------------------------------------------------------------------
// Feature kernel: one warp per (b, i) row; lanes stride over j.
// Distances handled in SQUARED domain (exact vs ref for mins by monotonicity;
// thresholds compared against squared constants).
// ---------------------------------------------------------------------------
__device__ __forceinline__ float wsum(float v) {
#pragma unroll
    for (int o = 16; o > 0; o >>= 1) v += __shfl_xor_sync(0xFFFFFFFFu, v, o);
    return v;
}
__device__ __forceinline__ float wmin(float v) {
#pragma unroll
    for (int o = 16; o > 0; o >>= 1) v = fminf(v, __shfl_xor_sync(0xFFFFFFFFu, v, o));
    return v;
}

__global__ __launch_bounds__(256) void feat_kernel(const float* __restrict__ pos,
                                                   const void* __restrict__ mask) {
    __shared__ float4 sp[NN];
    const int b   = blockIdx.y;
    const int tid = threadIdx.x;
    const int mode = g_maskmode;

    for (int idx = tid; idx < NN; idx += 256) {
        const int gi = b * NN + idx;
        float px = pos[gi * 2 + 0];
        float py = pos[gi * 2 + 1];
        bool m;
        if (mode == 1)      m = ((const unsigned char*)mask)[gi] != 0;
        else if (mode == 2) m = ((const float*)mask)[gi] != 0.0f;
        else                m = ((const int*)mask)[gi] != 0;
        sp[idx] = make_float4(px, py, m ? 0.0f : 1.0f, 0.0f);
    }
    __syncthreads();

    const int warp = tid >> 5, lane = tid & 31;
    const int i = blockIdx.x * 8 + warp;
    const float4 pi = sp[i];
    const float xi = pi.x, yi = pi.y;

    unsigned long long cntDT = 0ull;   // 12 counters: dir(0/20/40) x thresh(5-bit fields)
    unsigned scntLo = 0u, scntHi = 0u; // 8 sector counters, 8-bit fields
    float mdUp2 = LARGEF, mdDn2 = LARGEF, mdLat2 = LARGEF;
    float smin2[8];
#pragma unroll
    for (int k = 0; k < 8; k++) smin2[k] = LARGEF;
    float sumd = 0.0f, cntv = 0.0f;

#pragma unroll 4
    for (int j0 = 0; j0 < 16; j0++) {
        const int j = lane + (j0 << 5);
        const float4 p = sp[j];
        const float dx = p.x - xi;
        const float dy = p.y - yi;
        const float d2 = __fadd_rn(__fadd_rn(__fmul_rn(dx, dx), __fmul_rn(dy, dy)), 1e-8f);
        const bool  valid = (p.z != 0.0f) && (j != i);
        const float q2 = valid ? d2 : LARGEF;   // valid d2 <= ~800 << 1e6

        const float hay = 0.5f * fabsf(dy);
        const bool up = dx >  hay;
        const bool dn = dx < -hay;

        // cumulative thresholds, squared: 3^2,5^2,8^2,12^2
        unsigned pat = (q2 < 9.0f)   ? 0x8421u
                     : (q2 < 25.0f)  ? 0x8420u
                     : (q2 < 64.0f)  ? 0x8400u
                     : (q2 < 144.0f) ? 0x8000u : 0u;
        const int dsh = up ? 0 : (dn ? 20 : 40);
        cntDT += (unsigned long long)pat << dsh;

        mdUp2  = fminf(mdUp2,  up ? q2 : LARGEF);
        mdDn2  = fminf(mdDn2,  dn ? q2 : LARGEF);
        mdLat2 = fminf(mdLat2, (!up && !dn) ? q2 : LARGEF);

        // sector (octant) via sign tests
        const float su = dx + dy, sv = dy - dx;
        const int s = (dy < 0.0f)
            ? ((dx < 0.0f) ? ((sv > 0.0f) ? 0 : 1) : ((su < 0.0f) ? 2 : 3))
            : ((dx > 0.0f) ? ((sv < 0.0f) ? 4 : 5) : ((su > 0.0f) ? 6 : 7));

        const unsigned sinc = valid ? (1u << ((s & 3) << 3)) : 0u;
        if (s < 4) scntLo += sinc; else scntHi += sinc;
#pragma unroll
        for (int k = 0; k < 8; k++)
            if (s == k) smin2[k] = fminf(smin2[k], q2);

        // mean-distance sum: dist via rsqrt (smooth feature, mostly clamped)
        const float dist = d2 * rsqrtf(d2);
        sumd += valid ? dist : 0.0f;
        cntv += valid ? 1.0f : 0.0f;
    }

    float cnt[12];
#pragma unroll
    for (int d = 0; d < 3; d++)
#pragma unroll
        for (int t = 0; t < 4; t++)
            cnt[d * 4 + t] = (float)((unsigned)(cntDT >> (d * 20 + t * 5)) & 31u);
    float sc[8];
#pragma unroll
    for (int k = 0; k < 8; k++)
        sc[k] = (float)(((k < 4 ? (scntLo >> (k * 8)) : (scntHi >> ((k - 4) * 8)))) & 255u);

#pragma unroll
    for (int q = 0; q < 12; q++) cnt[q] = wsum(cnt[q]);
#pragma unroll
    for (int k = 0; k < 8; k++) { sc[k] = wsum(sc[k]); smin2[k] = wmin(smin2[k]); }
    mdUp2 = wmin(mdUp2); mdDn2 = wmin(mdDn2); mdLat2 = wmin(mdLat2);
    sumd = wsum(sumd); cntv = wsum(cntv);

    if (lane == 0) {
        float* o = g_feat + (size_t)(b * NN + i) * FEATN;
#pragma unroll
        for (int t = 0; t < 4; t++) {
            o[t * 3 + 0] = cnt[0 * 4 + t];
            o[t * 3 + 1] = cnt[1 * 4 + t];
            o[t * 3 + 2] = cnt[2 * 4 + t];
        }
        o[12] = fminf(sqrtf(mdUp2)  / 10.0f, 1.0f);
        o[13] = fminf(sqrtf(mdDn2)  / 10.0f, 1.0f);
        o[14] = fminf(sqrtf(mdLat2) / 10.0f, 1.0f);
#pragma unroll
        for (int k = 0; k < 8; k++) {
            o[15 + 2 * k] = sc[k];
            o[16 + 2 * k] = fminf(sqrtf(smin2[k]) / 10.0f, 1.0f);
        }
        o[31] = cnt[3] + cnt[7] + cnt[11];
        float vc = fmaxf(cntv, 1.0f);
        o[32] = fminf(sumd / vc / 10.0f, 1.0f);
    }
}

// ---------------------------------------------------------------------------
// Encoder v3: 64 rows/block, 256 threads. Thread = (cg = tid&63 -> cols 2cg,
// 2cg+1) x (rg = tid>>6 -> 16 rows). W1/W2 via __ldg float2 (L1/L2), x/h in
// shared (broadcast reads). Per k4 step: 4 LDG.64 + 16 LDS.128 + 256 FFMA.
// ---------------------------------------------------------------------------
#define XP 36
#define HP 132

__global__ __launch_bounds__(256, 3) void encoder_kernel(
    const float* __restrict__ W1, const float* __restrict__ b1,
    const float* __restrict__ gamma, const float* __restrict__ beta,
    const float* __restrict__ W2, const float* __restrict__ b2,
    float* __restrict__ out)
{
    __shared__ float sx[64 * XP];
    __shared__ float sh[64 * HP];
    __shared__ float sred[64 * 4];

    const int tid   = threadIdx.x;
    const int cg    = tid & 63;
    const int rg    = tid >> 6;        // 0..3
    const int lane  = tid & 31;
    const int whalf = cg >> 5;         // 0: cols 0..63, 1: cols 64..127
    const int c0    = cg * 2;
    const int r0    = rg * 16;
    const int rowBase = blockIdx.x * 64;

    for (int idx = tid; idx < 64 * FEATN; idx += 256) {
        int r = idx / FEATN, f = idx - r * FEATN;
        sx[r * XP + f] = g_feat[(size_t)rowBase * FEATN + idx];
    }
    for (int idx = tid; idx < 64 * 3; idx += 256) {
        int r = idx / 3;
        sx[r * XP + FEATN + idx % 3] = 0.0f;
    }
    __syncthreads();

    // ---- GEMM1: h = x @ W1 + b1, 16 rows x 2 cols per thread ----
    float accA[16], accB[16];
    {
        const float2 bb = __ldg((const float2*)&b1[c0]);
#pragma unroll
        for (int rr = 0; rr < 16; rr++) { accA[rr] = bb.x; accB[rr] = bb.y; }
#pragma unroll 2
        for (int f4 = 0; f4 < 32; f4 += 4) {
            const float2 w0 = __ldg((const float2*)&W1[(f4 + 0) * EE + c0]);
            const float2 w1 = __ldg((const float2*)&W1[(f4 + 1) * EE + c0]);
            const float2 w2 = __ldg((const float2*)&W1[(f4 + 2) * EE + c0]);
            const float2 w3 = __ldg((const float2*)&W1[(f4 + 3) * EE + c0]);
#pragma unroll
            for (int rr = 0; rr < 16; rr++) {
                const float4 xv = *(const float4*)&sx[(r0 + rr) * XP + f4];
                accA[rr] += xv.x * w0.x + xv.y * w1.x + xv.z * w2.x + xv.w * w3.x;
                accB[rr] += xv.x * w0.y + xv.y * w1.y + xv.z * w2.y + xv.w * w3.y;
            }
        }
        const float2 wl = __ldg((const float2*)&W1[32 * EE + c0]);
#pragma unroll
        for (int rr = 0; rr < 16; rr++) {
            const float xl = sx[(r0 + rr) * XP + 32];
            accA[rr] += xl * wl.x;
            accB[rr] += xl * wl.y;
        }
    }

    // ---- LN partials: each warp covers 64 columns of its rows ----
#pragma unroll
    for (int rr = 0; rr < 16; rr++) {
        float s  = wsum(accA[rr] + accB[rr]);
        float sq = wsum(accA[rr] * accA[rr] + accB[rr] * accB[rr]);
        if (lane == 0) {
            const int r = r0 + rr;
            sred[r * 4 + whalf * 2 + 0] = s;
            sred[r * 4 + whalf * 2 + 1] = sq;
        }
    }
    __syncthreads();

    const float2 gv  = __ldg((const float2*)&gamma[c0]);
    const float2 bev = __ldg((const float2*)&beta[c0]);
#pragma unroll
    for (int rr = 0; rr < 16; rr++) {
        const int r = r0 + rr;
        const float s  = sred[r * 4 + 0] + sred[r * 4 + 2];
        const float sq = sred[r * 4 + 1] + sred[r * 4 + 3];
        const float mu  = s * (1.0f / 128.0f);
        const float var = sq * (1.0f / 128.0f) - mu * mu;
        const float inv = 1.0f / sqrtf(var + 1e-5f);
        float hA = (accA[rr] - mu) * inv * gv.x + bev.x;
        float hB = (accB[rr] - mu) * inv * gv.y + bev.y;
        hA = 0.5f * hA * (1.0f + erff(hA * 0.70710678118654752440f));
        hB = 0.5f * hB * (1.0f + erff(hB * 0.70710678118654752440f));
        float2 hp = make_float2(hA, hB);
        *(float2*)&sh[r * HP + c0] = hp;
    }
    __syncthreads();

    // ---- GEMM2: out = h @ W2 + b2 ----
    float oA[16], oB[16];
    {
        const float2 bo = __ldg((const float2*)&b2[c0]);
#pragma unroll
        for (int rr = 0; rr < 16; rr++) { oA[rr] = bo.x; oB[rr] = bo.y; }
#pragma unroll 2
        for (int k4 = 0; k4 < EE; k4 += 4) {
            const float2 w0 = __ldg((const float2*)&W2[(k4 + 0) * EE + c0]);
            const float2 w1 = __ldg((const float2*)&W2[(k4 + 1) * EE + c0]);
            const float2 w2 = __ldg((const float2*)&W2[(k4 + 2) * EE + c0]);
            const float2 w3 = __ldg((const float2*)&W2[(k4 + 3) * EE + c0]);
#pragma unroll
            for (int rr = 0; rr < 16; rr++) {
                const float4 hv = *(const float4*)&sh[(r0 + rr) * HP + k4];
                oA[rr] += hv.x * w0.x + hv.y * w1.x + hv.z * w2.x + hv.w * w3.x;
                oB[rr] += hv.x * w0.y + hv.y * w1.y + hv.z * w2.y + hv.w * w3.y;
            }
        }
    }
#pragma unroll
    for (int rr = 0; rr < 16; rr++) {
        float2 o2 = make_float2(oA[rr], oB[rr]);
        *(float2*)&out[(size_t)(rowBase + r0 + rr) * EE + c0] = o2;
    }
}

// ---------------------------------------------------------------------------
extern "C" void kernel_launch(void* const* d_in, const int* in_sizes, int n_in,
                              void* d_out, int out_size) {
    const float* positions = (const float*)d_in[0];
    const void*  mask      = d_in[1];
    const float* W1        = (const float*)d_in[2];
    const float* b1        = (const float*)d_in[3];
    const float* gamma     = (const float*)d_in[4];
    const float* beta      = (const float*)d_in[5];
    const float* W2        = (const float*)d_in[6];
    const float* b2        = (const float*)d_in[7];
    float* out = (float*)d_out;

    detect_mask_kernel<<<1, 256>>>((const unsigned*)mask);
    feat_kernel<<<dim3(NN / 8, BB), 256>>>(positions, mask);
    encoder_kernel<<<ROWS / 64, 256>>>(W1, b1, gamma, beta, W2, b2, out);
}